// round 1
// baseline (speedup 1.0000x reference)
#include <cuda_runtime.h>
#include <math.h>

#define B_    32
#define H_    8
#define E_    64
#define M_    64
#define L_    1024
#define DOUT_ 64
#define HE    512    // H_*E_
#define M2    128    // 2*M_ (re|im packed)

// ---------------- device scratch (no allocations allowed) ----------------
__device__ float d_Tq[L_ * M2];            // forward twiddles for q modes [t][m2]
__device__ float d_Tk[L_ * M2];            // forward twiddles for k modes
__device__ float d_G [M2 * L_];            // inverse table [m2][t], includes 1/L and c_m
__device__ float d_Qf[B_ * HE * M2];       // q spectrum  [(b*512+he)][m2]
__device__ float d_Kf[B_ * HE * M2];       // k spectrum
__device__ float d_X2[B_ * H_ * DOUT_ * M2]; // xqkvw (scaled) [(b,h,o)][m2]

// ---------------- kernel 1: build twiddle tables (fp64 accurate) ----------
__global__ void build_tables_k(const int* __restrict__ iq, const int* __restrict__ ikv) {
    int t = blockIdx.x;      // 0..1023
    int j = threadIdx.x;     // 0..63
    const double TWO_PI = 6.283185307179586476925286766559;
    {
        int m = iq[j];
        int r = (m * t) & (L_ - 1);
        double a = TWO_PI * (double)r / (double)L_;
        double s = sin(a), c = cos(a);
        d_Tq[t * M2 + j]      = (float)c;       // Re: sum x*cos
        d_Tq[t * M2 + M_ + j] = (float)(-s);    // Im: -sum x*sin
        double cm = (m == 0 || m == L_ / 2) ? 1.0 : 2.0;
        // irfft: out[t] = (1/L) * sum_m c_m*(Xr*cos - Xi*sin); imag of DC drops (sin=0)
        d_G[j * L_ + t]        = (float)( cm * c / (double)L_);
        d_G[(M_ + j) * L_ + t] = (float)(-cm * s / (double)L_);
    }
    {
        int m = ikv[j];
        int r = (m * t) & (L_ - 1);
        double a = TWO_PI * (double)r / (double)L_;
        double s = sin(a), c = cos(a);
        d_Tk[t * M2 + j]      = (float)c;
        d_Tk[t * M2 + M_ + j] = (float)(-s);
    }
}

// ---------------- kernel 2: partial DFT as SGEMM -------------------------
// C[(b,he), m2] = sum_t x[b,t,he] * T[t,m2].   x: (B,1024,512). 128x128 tiles, K=1024.
__global__ __launch_bounds__(256) void dft_gemm_k(const float* __restrict__ qg,
                                                  const float* __restrict__ kg) {
    const int b   = blockIdx.y;
    const int he0 = blockIdx.x * 128;
    const int z   = blockIdx.z;
    const float* __restrict__ x = z ? kg : qg;
    const float* __restrict__ T = z ? d_Tk : d_Tq;
    float* __restrict__ outp    = z ? d_Kf : d_Qf;

    __shared__ float As[2][16][128];
    __shared__ float Ts[2][16][128];

    const int tid = threadIdx.x;
    const int rx  = (tid & 15) * 8;   // m2 offset
    const int ry  = (tid >> 4) * 8;   // he offset within tile

    float acc[8][8];
    #pragma unroll
    for (int i = 0; i < 8; i++)
        #pragma unroll
        for (int j = 0; j < 8; j++) acc[i][j] = 0.f;

    const float* xbase = x + (size_t)b * L_ * HE + he0;

    auto load = [&](int ks, int buf) {
        int k0 = ks * 16;
        #pragma unroll
        for (int r = 0; r < 2; r++) {
            int f  = tid + 256 * r;          // 0..511
            int kk = f >> 5;                 // 0..15
            int c  = (f & 31) << 2;          // 0..124
            float4 va = *(const float4*)(xbase + (size_t)(k0 + kk) * HE + c);
            *(float4*)&As[buf][kk][c] = va;
            float4 vt = *(const float4*)(T + (size_t)(k0 + kk) * M2 + c);
            *(float4*)&Ts[buf][kk][c] = vt;
        }
    };

    load(0, 0);
    __syncthreads();
    #pragma unroll 1
    for (int ks = 0; ks < 64; ks++) {
        int buf = ks & 1;
        if (ks + 1 < 64) load(ks + 1, buf ^ 1);
        #pragma unroll
        for (int kk = 0; kk < 16; kk++) {
            float4 a0 = *(float4*)&As[buf][kk][ry];
            float4 a1 = *(float4*)&As[buf][kk][ry + 4];
            float4 b0 = *(float4*)&Ts[buf][kk][rx];
            float4 b1 = *(float4*)&Ts[buf][kk][rx + 4];
            float av[8] = {a0.x,a0.y,a0.z,a0.w,a1.x,a1.y,a1.z,a1.w};
            float bv[8] = {b0.x,b0.y,b0.z,b0.w,b1.x,b1.y,b1.z,b1.w};
            #pragma unroll
            for (int i = 0; i < 8; i++)
                #pragma unroll
                for (int j = 0; j < 8; j++)
                    acc[i][j] += av[i] * bv[j];
        }
        __syncthreads();
    }

    float* dst = outp + ((size_t)b * HE + he0 + ry) * M2 + rx;
    #pragma unroll
    for (int i = 0; i < 8; i++) {
        *(float4*)(dst + (size_t)i * M2)     = make_float4(acc[i][0], acc[i][1], acc[i][2], acc[i][3]);
        *(float4*)(dst + (size_t)i * M2 + 4) = make_float4(acc[i][4], acc[i][5], acc[i][6], acc[i][7]);
    }
}

// ---------------- kernel 3: fused middle per (b,h) -----------------------
// stage2: xqk[x,y]=sum_e Qf[e,x]*Kf[e,y] (complex), tanh re/im
// stage3: xkv[e,x]=sum_y xqk[x,y]*Kf[e,y]
// stage4: X2[o,x] = (1/2^18) * sum_e xkv[e,x]*w[h,e,o,x]
__global__ __launch_bounds__(256) void middle_k(const float* __restrict__ wr_g,
                                                const float* __restrict__ wi_g) {
    extern __shared__ float sm[];
    float* Qs  = sm;            // [64][128]  32KB
    float* Ks  = sm + 8192;     // [64][128]  32KB
    float* qkr = sm + 16384;    // [y][x]     16KB
    float* qki = sm + 20480;    // [y][x]     16KB
    float* kvr = sm;            // alias over Qs  [e][x]
    float* kvi = sm + 4096;     // alias over Qs second half

    const int h = blockIdx.x, b = blockIdx.y;
    const int tid = threadIdx.x;

    const float* Qg = d_Qf + ((size_t)b * HE + h * E_) * M2;
    const float* Kg = d_Kf + ((size_t)b * HE + h * E_) * M2;
    for (int i = tid; i < E_ * M2 / 4; i += 256) {
        ((float4*)Qs)[i] = ((const float4*)Qg)[i];
        ((float4*)Ks)[i] = ((const float4*)Kg)[i];
    }
    __syncthreads();

    // ---- stage 2 ----
    {
        int x0 = (tid & 15) * 4, y0 = (tid >> 4) * 4;
        float ar[4][4], ai[4][4];
        #pragma unroll
        for (int yy = 0; yy < 4; yy++)
            #pragma unroll
            for (int xx = 0; xx < 4; xx++) { ar[yy][xx] = 0.f; ai[yy][xx] = 0.f; }
        #pragma unroll 4
        for (int e = 0; e < 64; e++) {
            float4 q4r = *(float4*)&Qs[e * 128 + x0];
            float4 q4i = *(float4*)&Qs[e * 128 + 64 + x0];
            float4 k4r = *(float4*)&Ks[e * 128 + y0];
            float4 k4i = *(float4*)&Ks[e * 128 + 64 + y0];
            float qrv[4] = {q4r.x,q4r.y,q4r.z,q4r.w};
            float qiv[4] = {q4i.x,q4i.y,q4i.z,q4i.w};
            float krv[4] = {k4r.x,k4r.y,k4r.z,k4r.w};
            float kiv[4] = {k4i.x,k4i.y,k4i.z,k4i.w};
            #pragma unroll
            for (int yy = 0; yy < 4; yy++)
                #pragma unroll
                for (int xx = 0; xx < 4; xx++) {
                    ar[yy][xx] += qrv[xx]*krv[yy] - qiv[xx]*kiv[yy];
                    ai[yy][xx] += qrv[xx]*kiv[yy] + qiv[xx]*krv[yy];
                }
        }
        #pragma unroll
        for (int yy = 0; yy < 4; yy++)
            #pragma unroll
            for (int xx = 0; xx < 4; xx++) {
                qkr[(y0 + yy) * 64 + x0 + xx] = tanhf(ar[yy][xx]);
                qki[(y0 + yy) * 64 + x0 + xx] = tanhf(ai[yy][xx]);
            }
    }
    __syncthreads();

    // ---- stage 3 ----
    {
        int x0 = (tid & 15) * 4, e0 = (tid >> 4) * 4;
        float cr[4][4], ci[4][4];
        #pragma unroll
        for (int ee = 0; ee < 4; ee++)
            #pragma unroll
            for (int xx = 0; xx < 4; xx++) { cr[ee][xx] = 0.f; ci[ee][xx] = 0.f; }
        #pragma unroll 4
        for (int y = 0; y < 64; y++) {
            float4 q4r = *(float4*)&qkr[y * 64 + x0];
            float4 q4i = *(float4*)&qki[y * 64 + x0];
            float qrv[4] = {q4r.x,q4r.y,q4r.z,q4r.w};
            float qiv[4] = {q4i.x,q4i.y,q4i.z,q4i.w};
            float krv[4], kiv[4];
            #pragma unroll
            for (int ee = 0; ee < 4; ee++) {
                krv[ee] = Ks[(e0 + ee) * 128 + y];
                kiv[ee] = Ks[(e0 + ee) * 128 + 64 + y];
            }
            #pragma unroll
            for (int ee = 0; ee < 4; ee++)
                #pragma unroll
                for (int xx = 0; xx < 4; xx++) {
                    cr[ee][xx] += qrv[xx]*krv[ee] - qiv[xx]*kiv[ee];
                    ci[ee][xx] += qrv[xx]*kiv[ee] + qiv[xx]*krv[ee];
                }
        }
        // kv aliases Qs: stage2 (last reader of Qs) completed at the sync above
        #pragma unroll
        for (int ee = 0; ee < 4; ee++)
            #pragma unroll
            for (int xx = 0; xx < 4; xx++) {
                kvr[(e0 + ee) * 64 + x0 + xx] = cr[ee][xx];
                kvi[(e0 + ee) * 64 + x0 + xx] = ci[ee][xx];
            }
    }
    __syncthreads();

    // ---- stage 4 ----
    {
        int x  = tid & 63;
        int o0 = (tid >> 6) * 16;
        float cr[16], ci[16];
        #pragma unroll
        for (int oo = 0; oo < 16; oo++) { cr[oo] = 0.f; ci[oo] = 0.f; }
        const float* wrp = wr_g + (size_t)h * E_ * DOUT_ * M_;
        const float* wip = wi_g + (size_t)h * E_ * DOUT_ * M_;
        #pragma unroll 1
        for (int e = 0; e < 64; e++) {
            float ar = kvr[e * 64 + x];
            float ai = kvi[e * 64 + x];
            size_t base = ((size_t)e * 64 + o0) * 64 + x;
            #pragma unroll
            for (int oo = 0; oo < 16; oo++) {
                float br = __ldg(wrp + base + (size_t)oo * 64);
                float bi = __ldg(wip + base + (size_t)oo * 64);
                cr[oo] += ar * br - ai * bi;
                ci[oo] += ar * bi + ai * br;
            }
        }
        const float S = 1.0f / 262144.0f;   // 1/(IN_CH*OUT_CH)
        size_t row0 = (size_t)(b * 8 + h) * 64 + o0;
        #pragma unroll
        for (int oo = 0; oo < 16; oo++) {
            d_X2[(row0 + oo) * M2 + x]       = cr[oo] * S;
            d_X2[(row0 + oo) * M2 + 64 + x]  = ci[oo] * S;
        }
    }
}

// ---------------- kernel 4: inverse (irfft) as SGEMM ----------------------
// out[row, t] = sum_{m2} X2[row, m2] * G[m2, t].  M=16384, K=128, N=1024.
__global__ __launch_bounds__(256) void inv_gemm_k(float* __restrict__ outp) {
    __shared__ float As[2][16][132];   // transposed X2 tile, padded
    __shared__ float Gs[2][16][128];

    const int t0  = blockIdx.x * 128;
    const int r0  = blockIdx.y * 128;
    const int tid = threadIdx.x;
    const int rx  = (tid & 15) * 8;
    const int ry  = (tid >> 4) * 8;

    float acc[8][8];
    #pragma unroll
    for (int i = 0; i < 8; i++)
        #pragma unroll
        for (int j = 0; j < 8; j++) acc[i][j] = 0.f;

    auto load = [&](int ks, int buf) {
        int k0 = ks * 16;
        #pragma unroll
        for (int rr = 0; rr < 2; rr++) {
            int f = tid + 256 * rr;          // 0..511
            int r = f >> 2;                  // 0..127 (row)
            int c = (f & 3) << 2;            // 0,4,8,12 (k)
            float4 v = *(const float4*)(d_X2 + (size_t)(r0 + r) * M2 + k0 + c);
            As[buf][c + 0][r] = v.x;
            As[buf][c + 1][r] = v.y;
            As[buf][c + 2][r] = v.z;
            As[buf][c + 3][r] = v.w;
            int kk = f >> 5;                 // 0..15
            int cg = (f & 31) << 2;          // 0..124
            float4 g = *(const float4*)(d_G + (size_t)(k0 + kk) * L_ + t0 + cg);
            *(float4*)&Gs[buf][kk][cg] = g;
        }
    };

    load(0, 0);
    __syncthreads();
    #pragma unroll 1
    for (int ks = 0; ks < 8; ks++) {
        int buf = ks & 1;
        if (ks + 1 < 8) load(ks + 1, buf ^ 1);
        #pragma unroll
        for (int kk = 0; kk < 16; kk++) {
            float4 a0 = *(float4*)&As[buf][kk][ry];
            float4 a1 = *(float4*)&As[buf][kk][ry + 4];
            float4 b0 = *(float4*)&Gs[buf][kk][rx];
            float4 b1 = *(float4*)&Gs[buf][kk][rx + 4];
            float av[8] = {a0.x,a0.y,a0.z,a0.w,a1.x,a1.y,a1.z,a1.w};
            float bv[8] = {b0.x,b0.y,b0.z,b0.w,b1.x,b1.y,b1.z,b1.w};
            #pragma unroll
            for (int i = 0; i < 8; i++)
                #pragma unroll
                for (int j = 0; j < 8; j++)
                    acc[i][j] += av[i] * bv[j];
        }
        __syncthreads();
    }

    float* dst = outp + (size_t)(r0 + ry) * L_ + t0 + rx;
    #pragma unroll
    for (int i = 0; i < 8; i++) {
        *(float4*)(dst + (size_t)i * L_)     = make_float4(acc[i][0], acc[i][1], acc[i][2], acc[i][3]);
        *(float4*)(dst + (size_t)i * L_ + 4) = make_float4(acc[i][4], acc[i][5], acc[i][6], acc[i][7]);
    }
}

// ---------------- launch ---------------------------------------------------
extern "C" void kernel_launch(void* const* d_in, const int* in_sizes, int n_in,
                              void* d_out, int out_size) {
    const float* q   = (const float*)d_in[0];
    const float* k   = (const float*)d_in[1];
    // d_in[2] (v) and d_in[3] (mask) are unused by the reference
    const float* wr  = (const float*)d_in[4];
    const float* wi  = (const float*)d_in[5];
    const int*   iq  = (const int*)d_in[6];
    const int*   ikv = (const int*)d_in[7];
    float* out = (float*)d_out;

    build_tables_k<<<L_, M_>>>(iq, ikv);
    dft_gemm_k<<<dim3(4, B_, 2), 256>>>(q, k);
    cudaFuncSetAttribute(middle_k, cudaFuncAttributeMaxDynamicSharedMemorySize, 98304);
    middle_k<<<dim3(H_, B_), 256, 98304>>>(wr, wi);
    inv_gemm_k<<<dim3(8, 128), 256>>>(out);
}

// round 2
// speedup vs baseline: 1.1955x; 1.1955x over previous
#include <cuda_runtime.h>
#include <math.h>

#define B_    32
#define H_    8
#define E_    64
#define M_    64
#define L_    1024
#define DOUT_ 64
#define HE    512
#define M2    128

// ---------------- device scratch ----------------
__device__ float d_Qf[B_ * HE * M2];          // q spectrum, natural [row][m2] (re 0..63 | im 64..127)
__device__ float d_Kf[B_ * HE * M2];          // k spectrum
__device__ float d_X2[B_ * H_ * DOUT_ * M2];  // xqkvw, class-sorted interleaved (re,im) pairs per slot

// forward fold twiddles (u<256): [t][64] cols = [Re slots 0..31 | Im slots 0..31]
__device__ float d_TEq[256 * 64], d_TAq[256 * 64], d_TBq[256 * 64];
__device__ float d_TEk[256 * 64], d_TAk[256 * 64], d_TBk[256 * 64];
// inverse tables (q modes), slot-major, t contiguous
__device__ float d_TRr[64 * 256], d_TRi[64 * 256], d_TIr[32 * 256], d_TIi[32 * 256];
// meta (class-sorted slot maps)
__device__ int d_slotm_q[64], d_slotm_k[64];
__device__ int d_evplane_q[32], d_evplane_k[32];
__device__ int d_ncolE_q[64], d_ncolO_q[64], d_ncolE_k[64], d_ncolO_k[64];
__device__ int d_pos2slot_q[64];
__device__ int d_bnd_q[2];   // [0]=end of class0 slots, [1]=end of class1 slots (in 32..64)

// ---------------- meta: class-sort modes (order 0,2,1,3) ------------------
__global__ void meta_k(const int* __restrict__ iq, const int* __restrict__ ikv) {
    for (int z = 0; z < 2; z++) {
        const int* ix = z ? ikv : iq;
        int* slotm = z ? d_slotm_k : d_slotm_q;
        int* evpl  = z ? d_evplane_k : d_evplane_q;
        int* ncE   = z ? d_ncolE_k : d_ncolE_q;
        int* ncO   = z ? d_ncolO_k : d_ncolO_q;
        int s2p[64];
        int cnt = 0;
        const int order[4] = {0, 2, 1, 3};
        int cend[4];
        for (int ci = 0; ci < 4; ci++) {
            int c = order[ci];
            for (int j = 0; j < 64; j++) {
                int m = ix[j];
                if ((m & 3) == c) {
                    slotm[cnt] = m;
                    s2p[cnt] = j;
                    if (cnt < 32) evpl[cnt] = (c == 2) ? 1 : 0;
                    if (!z) d_pos2slot_q[j] = cnt;
                    cnt++;
                }
            }
            cend[ci] = cnt;
        }
        for (int j = 0; j < 64; j++) {
            ncE[j] = (j < 32 ? 0 : 64) + s2p[j & 31];
            ncO[j] = (j < 32 ? 0 : 64) + s2p[32 + (j & 31)];
        }
        if (!z) { d_bnd_q[0] = cend[0]; d_bnd_q[1] = cend[2]; }
    }
}

// ---------------- tables (fp64 accurate) ----------------------------------
__global__ void tables_k() {
    int t = blockIdx.x;   // 0..255
    int j = threadIdx.x;  // 0..63 (slot)
    const double C = 6.283185307179586476925286766559 / (double)L_;
    for (int z = 0; z < 2; z++) {
        const int* slotm = z ? d_slotm_k : d_slotm_q;
        float* TE = z ? d_TEk : d_TEq;
        float* TA = z ? d_TAk : d_TAq;
        float* TB = z ? d_TBk : d_TBq;
        int m = slotm[j];
        double th = C * (double)((m * t) & (L_ - 1));
        double cs = cos(th), sn = sin(th);
        if (j < 32) {
            TE[t * 64 + j]      = (float)cs;
            TE[t * 64 + 32 + j] = (float)(-sn);
        } else {
            int s = j - 32;
            TA[t * 64 + s]      = (float)cs;
            TA[t * 64 + 32 + s] = (float)(-sn);
            double sg = ((m & 3) == 1) ? -1.0 : 1.0;
            TB[t * 64 + s]      = (float)(sg * sn);
            TB[t * 64 + 32 + s] = (float)(sg * cs);
        }
    }
    {
        int m = d_slotm_q[j];
        double th = C * (double)((m * t) & (L_ - 1));
        double g = ((m == 0) || (2 * m == L_)) ? (1.0 / L_) : (2.0 / L_);
        d_TRr[j * 256 + t] = (float)( g * cos(th));
        d_TRi[j * 256 + t] = (float)(-g * sin(th));
        if (j >= 32) {
            d_TIr[(j - 32) * 256 + t] = (float)(g * sin(th));
            d_TIi[(j - 32) * 256 + t] = (float)(g * cos(th));
        }
    }
}

// ---------------- forward: folded partial DFT ------------------------------
// Block: 128x64 tile. blockIdx.x: bit0=half (0=even-mode cols, 1=odd), >>1 = heTile.
__global__ __launch_bounds__(128) void dft_fold_k(const float* __restrict__ qg,
                                                  const float* __restrict__ kg) {
    extern __shared__ float sm[];
    float* PL = sm;          // [2 buf][16 kk][2 pl][128]
    float* TW = sm + 8192;   // [2 buf][16 kk][2][64]
    const int heTile = blockIdx.x >> 1;
    const int half   = blockIdx.x & 1;
    const int b      = blockIdx.y;
    const int zin    = blockIdx.z;
    const float* __restrict__ x = zin ? kg : qg;
    float* outp = zin ? d_Kf : d_Qf;
    const float* __restrict__ Tmain = half ? (zin ? d_TAk : d_TAq) : (zin ? d_TEk : d_TEq);
    const float* __restrict__ Tsec  = zin ? d_TBk : d_TBq;
    const int* __restrict__ ncol = half ? (zin ? d_ncolO_k : d_ncolO_q)
                                        : (zin ? d_ncolE_k : d_ncolE_q);
    const int he0 = heTile * 128;
    const int tid = threadIdx.x;
    const int rx  = (tid & 7) * 8;
    const int ry  = (tid >> 3) * 8;
    const int pl  = half ? 0 : (zin ? d_evplane_k : d_evplane_q)[rx & 31];
    const float* xb = x + (size_t)b * (L_ * HE) + he0;

    float acc[8][8];
    #pragma unroll
    for (int i = 0; i < 8; i++)
        #pragma unroll
        for (int j = 0; j < 8; j++) acc[i][j] = 0.f;

    auto load = [&](int ks, int buf, bool hf) {
        int u0 = ks * 16;
        float* plb = PL + buf * 4096;
        #pragma unroll
        for (int r = 0; r < 4; r++) {
            int idx = tid + 128 * r;
            int ul  = idx >> 5;
            int c4  = (idx & 31) * 4;
            const float* p = xb + (size_t)(u0 + ul) * HE + c4;
            float4 x0 = *(const float4*)p;
            float4 x1 = *(const float4*)(p + 256 * HE);
            float4 x2 = *(const float4*)(p + 512 * HE);
            float4 x3 = *(const float4*)(p + 768 * HE);
            float4 P, Q;
            if (hf) {
                P.x = x0.x - x2.x; P.y = x0.y - x2.y; P.z = x0.z - x2.z; P.w = x0.w - x2.w;
                Q.x = x1.x - x3.x; Q.y = x1.y - x3.y; Q.z = x1.z - x3.z; Q.w = x1.w - x3.w;
            } else {
                float4 e0, e1;
                e0.x = x0.x + x2.x; e0.y = x0.y + x2.y; e0.z = x0.z + x2.z; e0.w = x0.w + x2.w;
                e1.x = x1.x + x3.x; e1.y = x1.y + x3.y; e1.z = x1.z + x3.z; e1.w = x1.w + x3.w;
                P.x = e0.x + e1.x; P.y = e0.y + e1.y; P.z = e0.z + e1.z; P.w = e0.w + e1.w;
                Q.x = e0.x - e1.x; Q.y = e0.y - e1.y; Q.z = e0.z - e1.z; Q.w = e0.w - e1.w;
            }
            *(float4*)&plb[(ul * 2 + 0) * 128 + c4] = P;
            *(float4*)&plb[(ul * 2 + 1) * 128 + c4] = Q;
        }
        float* twb = TW + buf * 2048;
        #pragma unroll
        for (int r = 0; r < 2; r++) {
            int f = tid + 128 * r;
            int row = f >> 4, c4 = (f & 15) * 4;
            *(float4*)&twb[(row * 2 + 0) * 64 + c4] = *(const float4*)&Tmain[(u0 + row) * 64 + c4];
            if (hf)
                *(float4*)&twb[(row * 2 + 1) * 64 + c4] = *(const float4*)&Tsec[(u0 + row) * 64 + c4];
        }
    };

    if (half) {
        load(0, 0, true);
        __syncthreads();
        #pragma unroll 1
        for (int ks = 0; ks < 16; ks++) {
            int buf = ks & 1;
            if (ks + 1 < 16) load(ks + 1, buf ^ 1, true);
            float* plb = PL + buf * 4096;
            float* twb = TW + buf * 2048;
            #pragma unroll
            for (int kk = 0; kk < 16; kk++) {
                float av[8], bv[8], ca[8], cb[8];
                *(float4*)&av[0] = *(float4*)&plb[kk * 256 + ry];
                *(float4*)&av[4] = *(float4*)&plb[kk * 256 + ry + 4];
                *(float4*)&bv[0] = *(float4*)&plb[kk * 256 + 128 + ry];
                *(float4*)&bv[4] = *(float4*)&plb[kk * 256 + 128 + ry + 4];
                *(float4*)&ca[0] = *(float4*)&twb[kk * 128 + rx];
                *(float4*)&ca[4] = *(float4*)&twb[kk * 128 + rx + 4];
                *(float4*)&cb[0] = *(float4*)&twb[kk * 128 + 64 + rx];
                *(float4*)&cb[4] = *(float4*)&twb[kk * 128 + 64 + rx + 4];
                #pragma unroll
                for (int i = 0; i < 8; i++)
                    #pragma unroll
                    for (int j = 0; j < 8; j++)
                        acc[i][j] += av[i] * ca[j] + bv[i] * cb[j];
            }
            __syncthreads();
        }
    } else {
        load(0, 0, false);
        __syncthreads();
        #pragma unroll 1
        for (int ks = 0; ks < 16; ks++) {
            int buf = ks & 1;
            if (ks + 1 < 16) load(ks + 1, buf ^ 1, false);
            float* plb = PL + buf * 4096;
            float* twb = TW + buf * 2048;
            #pragma unroll
            for (int kk = 0; kk < 16; kk++) {
                float av[8], bv[8];
                *(float4*)&av[0] = *(float4*)&plb[kk * 256 + pl * 128 + ry];
                *(float4*)&av[4] = *(float4*)&plb[kk * 256 + pl * 128 + ry + 4];
                *(float4*)&bv[0] = *(float4*)&twb[kk * 128 + rx];
                *(float4*)&bv[4] = *(float4*)&twb[kk * 128 + rx + 4];
                #pragma unroll
                for (int i = 0; i < 8; i++)
                    #pragma unroll
                    for (int j = 0; j < 8; j++)
                        acc[i][j] += av[i] * bv[j];
            }
            __syncthreads();
        }
    }

    int nc[8];
    #pragma unroll
    for (int j = 0; j < 8; j++) nc[j] = ncol[rx + j];
    float* dst = outp + ((size_t)b * HE + he0 + ry) * M2;
    #pragma unroll
    for (int i = 0; i < 8; i++)
        #pragma unroll
        for (int j = 0; j < 8; j++)
            dst[(size_t)i * M2 + nc[j]] = acc[i][j];
}

// ---------------- middle (unchanged math; slot-permuted X2 write) ----------
__global__ __launch_bounds__(256) void middle_k(const float* __restrict__ wr_g,
                                                const float* __restrict__ wi_g) {
    extern __shared__ float sm[];
    float* Qs  = sm;
    float* Ks  = sm + 8192;
    float* qkr = sm + 16384;
    float* qki = sm + 20480;
    float* kvr = sm;
    float* kvi = sm + 4096;

    const int h = blockIdx.x, b = blockIdx.y;
    const int tid = threadIdx.x;

    const float* Qg = d_Qf + ((size_t)b * HE + h * E_) * M2;
    const float* Kg = d_Kf + ((size_t)b * HE + h * E_) * M2;
    for (int i = tid; i < E_ * M2 / 4; i += 256) {
        ((float4*)Qs)[i] = ((const float4*)Qg)[i];
        ((float4*)Ks)[i] = ((const float4*)Kg)[i];
    }
    __syncthreads();

    {
        int x0 = (tid & 15) * 4, y0 = (tid >> 4) * 4;
        float ar[4][4], ai[4][4];
        #pragma unroll
        for (int yy = 0; yy < 4; yy++)
            #pragma unroll
            for (int xx = 0; xx < 4; xx++) { ar[yy][xx] = 0.f; ai[yy][xx] = 0.f; }
        #pragma unroll 4
        for (int e = 0; e < 64; e++) {
            float4 q4r = *(float4*)&Qs[e * 128 + x0];
            float4 q4i = *(float4*)&Qs[e * 128 + 64 + x0];
            float4 k4r = *(float4*)&Ks[e * 128 + y0];
            float4 k4i = *(float4*)&Ks[e * 128 + 64 + y0];
            float qrv[4] = {q4r.x,q4r.y,q4r.z,q4r.w};
            float qiv[4] = {q4i.x,q4i.y,q4i.z,q4i.w};
            float krv[4] = {k4r.x,k4r.y,k4r.z,k4r.w};
            float kiv[4] = {k4i.x,k4i.y,k4i.z,k4i.w};
            #pragma unroll
            for (int yy = 0; yy < 4; yy++)
                #pragma unroll
                for (int xx = 0; xx < 4; xx++) {
                    ar[yy][xx] += qrv[xx]*krv[yy] - qiv[xx]*kiv[yy];
                    ai[yy][xx] += qrv[xx]*kiv[yy] + qiv[xx]*krv[yy];
                }
        }
        #pragma unroll
        for (int yy = 0; yy < 4; yy++)
            #pragma unroll
            for (int xx = 0; xx < 4; xx++) {
                qkr[(y0 + yy) * 64 + x0 + xx] = tanhf(ar[yy][xx]);
                qki[(y0 + yy) * 64 + x0 + xx] = tanhf(ai[yy][xx]);
            }
    }
    __syncthreads();

    {
        int x0 = (tid & 15) * 4, e0 = (tid >> 4) * 4;
        float cr[4][4], ci[4][4];
        #pragma unroll
        for (int ee = 0; ee < 4; ee++)
            #pragma unroll
            for (int xx = 0; xx < 4; xx++) { cr[ee][xx] = 0.f; ci[ee][xx] = 0.f; }
        #pragma unroll 4
        for (int y = 0; y < 64; y++) {
            float4 q4r = *(float4*)&qkr[y * 64 + x0];
            float4 q4i = *(float4*)&qki[y * 64 + x0];
            float qrv[4] = {q4r.x,q4r.y,q4r.z,q4r.w};
            float qiv[4] = {q4i.x,q4i.y,q4i.z,q4i.w};
            float krv[4], kiv[4];
            #pragma unroll
            for (int ee = 0; ee < 4; ee++) {
                krv[ee] = Ks[(e0 + ee) * 128 + y];
                kiv[ee] = Ks[(e0 + ee) * 128 + 64 + y];
            }
            #pragma unroll
            for (int ee = 0; ee < 4; ee++)
                #pragma unroll
                for (int xx = 0; xx < 4; xx++) {
                    cr[ee][xx] += qrv[xx]*krv[ee] - qiv[xx]*kiv[ee];
                    ci[ee][xx] += qrv[xx]*kiv[ee] + qiv[xx]*krv[ee];
                }
        }
        #pragma unroll
        for (int ee = 0; ee < 4; ee++)
            #pragma unroll
            for (int xx = 0; xx < 4; xx++) {
                kvr[(e0 + ee) * 64 + x0 + xx] = cr[ee][xx];
                kvi[(e0 + ee) * 64 + x0 + xx] = ci[ee][xx];
            }
    }
    __syncthreads();

    {
        int x  = tid & 63;
        int o0 = (tid >> 6) * 16;
        float cr[16], ci[16];
        #pragma unroll
        for (int oo = 0; oo < 16; oo++) { cr[oo] = 0.f; ci[oo] = 0.f; }
        const float* wrp = wr_g + (size_t)h * E_ * DOUT_ * M_;
        const float* wip = wi_g + (size_t)h * E_ * DOUT_ * M_;
        #pragma unroll 1
        for (int e = 0; e < 64; e++) {
            float ar = kvr[e * 64 + x];
            float ai = kvi[e * 64 + x];
            size_t base = ((size_t)e * 64 + o0) * 64 + x;
            #pragma unroll
            for (int oo = 0; oo < 16; oo++) {
                float br = __ldg(wrp + base + (size_t)oo * 64);
                float bi = __ldg(wip + base + (size_t)oo * 64);
                cr[oo] += ar * br - ai * bi;
                ci[oo] += ar * bi + ai * br;
            }
        }
        const float S = 1.0f / 262144.0f;
        int slot = d_pos2slot_q[x];
        size_t row0 = (size_t)(b * 8 + h) * 64 + o0;
        #pragma unroll
        for (int oo = 0; oo < 16; oo++) {
            d_X2[(row0 + oo) * M2 + 2 * slot]     = cr[oo] * S;
            d_X2[(row0 + oo) * M2 + 2 * slot + 1] = ci[oo] * S;
        }
    }
}

// ---------------- inverse: folded irfft ------------------------------------
__global__ __launch_bounds__(256) void inv_fold_k(float* __restrict__ outp) {
    extern __shared__ float sm[];
    float* Ys = sm;             // [64][128]
    float* Rr = sm + 8192;      // [64][64]
    float* Ri = sm + 12288;
    float* Ir = sm + 16384;     // [32][64]
    float* Ii = sm + 18432;
    const int u0 = blockIdx.x * 64;
    const int r0 = blockIdx.y * 64;
    const int tid = threadIdx.x;

    {
        const float4* src = (const float4*)(d_X2 + (size_t)r0 * M2);
        for (int i = tid; i < 2048; i += 256) ((float4*)Ys)[i] = src[i];
        for (int i = tid; i < 1024; i += 256) {
            int s = i >> 4, c4 = (i & 15) * 4;
            *(float4*)&Rr[s * 64 + c4] = *(const float4*)&d_TRr[s * 256 + u0 + c4];
            *(float4*)&Ri[s * 64 + c4] = *(const float4*)&d_TRi[s * 256 + u0 + c4];
        }
        for (int i = tid; i < 512; i += 256) {
            int s = i >> 4, c4 = (i & 15) * 4;
            *(float4*)&Ir[s * 64 + c4] = *(const float4*)&d_TIr[s * 256 + u0 + c4];
            *(float4*)&Ii[s * 64 + c4] = *(const float4*)&d_TIi[s * 256 + u0 + c4];
        }
    }
    __syncthreads();

    const int rr = (tid >> 4) * 4;
    const int uu = (tid & 15) * 4;
    float R0[4][4] = {}, R2[4][4] = {}, R1[4][4] = {}, I1[4][4] = {}, R3[4][4] = {}, I3[4][4] = {};

    const int n0 = d_bnd_q[0], n1 = d_bnd_q[1];

#define ACC_R(S, AR) { \
    float4 c4v = *(float4*)&Rr[(S) * 64 + uu]; \
    float4 d4v = *(float4*)&Ri[(S) * 64 + uu]; \
    float cv[4] = {c4v.x,c4v.y,c4v.z,c4v.w}; \
    float dv[4] = {d4v.x,d4v.y,d4v.z,d4v.w}; \
    _Pragma("unroll") \
    for (int r_ = 0; r_ < 4; r_++) { \
        float2 y = *(float2*)&Ys[(rr + r_) * 128 + 2 * (S)]; \
        _Pragma("unroll") \
        for (int u_ = 0; u_ < 4; u_++) AR[r_][u_] += y.x * cv[u_] + y.y * dv[u_]; \
    } }

#define ACC_RI(S, AR, AI) { \
    float4 c4v = *(float4*)&Rr[(S) * 64 + uu]; \
    float4 d4v = *(float4*)&Ri[(S) * 64 + uu]; \
    float4 e4v = *(float4*)&Ir[((S) - 32) * 64 + uu]; \
    float4 f4v = *(float4*)&Ii[((S) - 32) * 64 + uu]; \
    float cv[4] = {c4v.x,c4v.y,c4v.z,c4v.w}; \
    float dv[4] = {d4v.x,d4v.y,d4v.z,d4v.w}; \
    float ev[4] = {e4v.x,e4v.y,e4v.z,e4v.w}; \
    float fv[4] = {f4v.x,f4v.y,f4v.z,f4v.w}; \
    _Pragma("unroll") \
    for (int r_ = 0; r_ < 4; r_++) { \
        float2 y = *(float2*)&Ys[(rr + r_) * 128 + 2 * (S)]; \
        _Pragma("unroll") \
        for (int u_ = 0; u_ < 4; u_++) { \
            AR[r_][u_] += y.x * cv[u_] + y.y * dv[u_]; \
            AI[r_][u_] += y.x * ev[u_] + y.y * fv[u_]; \
        } \
    } }

    for (int s = 0; s < n0; s++)  ACC_R(s, R0);
    for (int s = n0; s < 32; s++) ACC_R(s, R2);
    for (int s = 32; s < n1; s++) ACC_RI(s, R1, I1);
    for (int s = n1; s < 64; s++) ACC_RI(s, R3, I3);

#undef ACC_R
#undef ACC_RI

    #pragma unroll
    for (int r_ = 0; r_ < 4; r_++) {
        float o0[4], o1[4], o2[4], o3[4];
        #pragma unroll
        for (int u_ = 0; u_ < 4; u_++) {
            float rp = R0[r_][u_] + R2[r_][u_];
            float rm = R0[r_][u_] - R2[r_][u_];
            o0[u_] = rp + R1[r_][u_] + R3[r_][u_];
            o1[u_] = rm - I1[r_][u_] + I3[r_][u_];
            o2[u_] = rp - R1[r_][u_] - R3[r_][u_];
            o3[u_] = rm + I1[r_][u_] - I3[r_][u_];
        }
        float* dst = outp + (size_t)(r0 + rr + r_) * L_ + u0 + uu;
        *(float4*)(dst + 0)   = make_float4(o0[0], o0[1], o0[2], o0[3]);
        *(float4*)(dst + 256) = make_float4(o1[0], o1[1], o1[2], o1[3]);
        *(float4*)(dst + 512) = make_float4(o2[0], o2[1], o2[2], o2[3]);
        *(float4*)(dst + 768) = make_float4(o3[0], o3[1], o3[2], o3[3]);
    }
}

// ---------------- launch ---------------------------------------------------
extern "C" void kernel_launch(void* const* d_in, const int* in_sizes, int n_in,
                              void* d_out, int out_size) {
    const float* q   = (const float*)d_in[0];
    const float* k   = (const float*)d_in[1];
    const float* wr  = (const float*)d_in[4];
    const float* wi  = (const float*)d_in[5];
    const int*   iq  = (const int*)d_in[6];
    const int*   ikv = (const int*)d_in[7];
    float* out = (float*)d_out;

    meta_k<<<1, 1>>>(iq, ikv);
    tables_k<<<256, 64>>>();
    cudaFuncSetAttribute(dft_fold_k, cudaFuncAttributeMaxDynamicSharedMemorySize, 49152);
    dft_fold_k<<<dim3(8, B_, 2), 128, 49152>>>(q, k);
    cudaFuncSetAttribute(middle_k, cudaFuncAttributeMaxDynamicSharedMemorySize, 98304);
    middle_k<<<dim3(H_, B_), 256, 98304>>>(wr, wi);
    cudaFuncSetAttribute(inv_fold_k, cudaFuncAttributeMaxDynamicSharedMemorySize, 81920);
    inv_fold_k<<<dim3(4, 256), 256, 81920>>>(out);
}

// round 3
// speedup vs baseline: 1.2825x; 1.0727x over previous
#include <cuda_runtime.h>
#include <math.h>

#define B_    32
#define H_    8
#define E_    64
#define M_    64
#define L_    1024
#define DOUT_ 64
#define HE    512
#define M2    128

// ---------------- device scratch ----------------
__device__ float d_Qf[B_ * HE * M2];          // q spectrum, natural [row][m2]
__device__ float d_Kf[B_ * HE * M2];          // k spectrum
__device__ float d_KV[512 * 2 * 2048];        // kv: [(h*64+x)][c][b*64+e]
__device__ float d_WTr[8 * 64 * 64 * 64];     // wT [h][m][e][o]
__device__ float d_WTi[8 * 64 * 64 * 64];
__device__ float d_X2T[128 * 16384];          // X2 transposed: [2*slot+c][(b*8+h)*64+o]

// forward fold twiddles
__device__ float d_TEq[256 * 64], d_TAq[256 * 64], d_TBq[256 * 64];
__device__ float d_TEk[256 * 64], d_TAk[256 * 64], d_TBk[256 * 64];
// inverse tables
__device__ float d_TRr[64 * 256], d_TRi[64 * 256], d_TIr[32 * 256], d_TIi[32 * 256];
// meta
__device__ int d_slotm_q[64], d_slotm_k[64];
__device__ int d_evplane_q[32], d_evplane_k[32];
__device__ int d_ncolE_q[64], d_ncolO_q[64], d_ncolE_k[64], d_ncolO_k[64];
__device__ int d_pos2slot_q[64];
__device__ int d_bnd_q[2];

// ---------------- meta: parallel class-sort (order 0,2,1,3) ---------------
__global__ void meta_k(const int* __restrict__ iq, const int* __restrict__ ikv) {
    int z = blockIdx.x, j = threadIdx.x;
    __shared__ int mA[64], s2p[64], keys[64];
    const int* ix = z ? ikv : iq;
    mA[j] = ix[j];
    __syncthreads();
    int m = mA[j], c = m & 3;
    int oidx = (c == 0) ? 0 : ((c == 2) ? 1 : ((c == 1) ? 2 : 3));
    keys[j] = oidx * 64 + j;
    __syncthreads();
    int key = keys[j], slot = 0;
    for (int t = 0; t < 64; t++) slot += (keys[t] < key);
    (z ? d_slotm_k : d_slotm_q)[slot] = m;
    s2p[slot] = j;
    if (slot < 32) (z ? d_evplane_k : d_evplane_q)[slot] = (c == 2) ? 1 : 0;
    if (!z) d_pos2slot_q[j] = slot;
    __syncthreads();
    int* ncE = z ? d_ncolE_k : d_ncolE_q;
    int* ncO = z ? d_ncolO_k : d_ncolO_q;
    ncE[j] = (j < 32 ? 0 : 64) + s2p[j & 31];
    ncO[j] = (j < 32 ? 0 : 64) + s2p[32 + (j & 31)];
    if (!z && j == 0) {
        int c0 = 0, c1 = 0, c2 = 0;
        for (int t = 0; t < 64; t++) {
            int cc = mA[t] & 3;
            c0 += (cc == 0); c1 += (cc == 1); c2 += (cc == 2);
        }
        d_bnd_q[0] = c0;
        d_bnd_q[1] = c0 + c2 + c1;
    }
}

// ---------------- tables (fp64 accurate) ----------------------------------
__global__ void tables_k() {
    int t = blockIdx.x;
    int j = threadIdx.x;
    const double C = 6.283185307179586476925286766559 / (double)L_;
    for (int z = 0; z < 2; z++) {
        const int* slotm = z ? d_slotm_k : d_slotm_q;
        float* TE = z ? d_TEk : d_TEq;
        float* TA = z ? d_TAk : d_TAq;
        float* TB = z ? d_TBk : d_TBq;
        int m = slotm[j];
        double th = C * (double)((m * t) & (L_ - 1));
        double cs = cos(th), sn = sin(th);
        if (j < 32) {
            TE[t * 64 + j]      = (float)cs;
            TE[t * 64 + 32 + j] = (float)(-sn);
        } else {
            int s = j - 32;
            TA[t * 64 + s]      = (float)cs;
            TA[t * 64 + 32 + s] = (float)(-sn);
            double sg = ((m & 3) == 1) ? -1.0 : 1.0;
            TB[t * 64 + s]      = (float)(sg * sn);
            TB[t * 64 + 32 + s] = (float)(sg * cs);
        }
    }
    {
        int m = d_slotm_q[j];
        double th = C * (double)((m * t) & (L_ - 1));
        double g = ((m == 0) || (2 * m == L_)) ? (1.0 / L_) : (2.0 / L_);
        d_TRr[j * 256 + t] = (float)( g * cos(th));
        d_TRi[j * 256 + t] = (float)(-g * sin(th));
        if (j >= 32) {
            d_TIr[(j - 32) * 256 + t] = (float)(g * sin(th));
            d_TIi[(j - 32) * 256 + t] = (float)(g * cos(th));
        }
    }
}

// ---------------- w transpose: (H,E,DOUT,M) -> (H,M,E,DOUT) ----------------
__global__ __launch_bounds__(256) void wtrans_k(const float* __restrict__ wr_g,
                                                const float* __restrict__ wi_g) {
    __shared__ float tile[32][33];
    const int ot = (blockIdx.x & 1) * 32;
    const int mt = (blockIdx.x >> 1) * 32;
    const int e  = blockIdx.y;
    const int h  = blockIdx.z;
    const int r  = threadIdx.x >> 3;
    const int c4 = (threadIdx.x & 7) * 4;

    for (int z = 0; z < 2; z++) {
        const float* src = z ? wi_g : wr_g;
        float* dst = z ? d_WTi : d_WTr;
        float4 v = *(const float4*)&src[((size_t)(h * 64 + e) * 64 + ot + r) * 64 + mt + c4];
        tile[r][c4 + 0] = v.x; tile[r][c4 + 1] = v.y;
        tile[r][c4 + 2] = v.z; tile[r][c4 + 3] = v.w;
        __syncthreads();
        float4 o;
        o.x = tile[c4 + 0][r]; o.y = tile[c4 + 1][r];
        o.z = tile[c4 + 2][r]; o.w = tile[c4 + 3][r];
        *(float4*)&dst[((size_t)(h * 64 + mt + r) * 64 + e) * 64 + ot + c4] = o;
        __syncthreads();
    }
}

// ---------------- forward: folded partial DFT (unchanged) ------------------
__global__ __launch_bounds__(128) void dft_fold_k(const float* __restrict__ qg,
                                                  const float* __restrict__ kg) {
    extern __shared__ float sm[];
    float* PL = sm;
    float* TW = sm + 8192;
    const int heTile = blockIdx.x >> 1;
    const int half   = blockIdx.x & 1;
    const int b      = blockIdx.y;
    const int zin    = blockIdx.z;
    const float* __restrict__ x = zin ? kg : qg;
    float* outp = zin ? d_Kf : d_Qf;
    const float* __restrict__ Tmain = half ? (zin ? d_TAk : d_TAq) : (zin ? d_TEk : d_TEq);
    const float* __restrict__ Tsec  = zin ? d_TBk : d_TBq;
    const int* __restrict__ ncol = half ? (zin ? d_ncolO_k : d_ncolO_q)
                                        : (zin ? d_ncolE_k : d_ncolE_q);
    const int he0 = heTile * 128;
    const int tid = threadIdx.x;
    const int rx  = (tid & 7) * 8;
    const int ry  = (tid >> 3) * 8;
    const int pl  = half ? 0 : (zin ? d_evplane_k : d_evplane_q)[rx & 31];
    const float* xb = x + (size_t)b * (L_ * HE) + he0;

    float acc[8][8];
    #pragma unroll
    for (int i = 0; i < 8; i++)
        #pragma unroll
        for (int j = 0; j < 8; j++) acc[i][j] = 0.f;

    auto load = [&](int ks, int buf, bool hf) {
        int u0 = ks * 16;
        float* plb = PL + buf * 4096;
        #pragma unroll
        for (int r = 0; r < 4; r++) {
            int idx = tid + 128 * r;
            int ul  = idx >> 5;
            int c4  = (idx & 31) * 4;
            const float* p = xb + (size_t)(u0 + ul) * HE + c4;
            float4 x0 = *(const float4*)p;
            float4 x1 = *(const float4*)(p + 256 * HE);
            float4 x2 = *(const float4*)(p + 512 * HE);
            float4 x3 = *(const float4*)(p + 768 * HE);
            float4 P, Q;
            if (hf) {
                P.x = x0.x - x2.x; P.y = x0.y - x2.y; P.z = x0.z - x2.z; P.w = x0.w - x2.w;
                Q.x = x1.x - x3.x; Q.y = x1.y - x3.y; Q.z = x1.z - x3.z; Q.w = x1.w - x3.w;
            } else {
                float4 e0, e1;
                e0.x = x0.x + x2.x; e0.y = x0.y + x2.y; e0.z = x0.z + x2.z; e0.w = x0.w + x2.w;
                e1.x = x1.x + x3.x; e1.y = x1.y + x3.y; e1.z = x1.z + x3.z; e1.w = x1.w + x3.w;
                P.x = e0.x + e1.x; P.y = e0.y + e1.y; P.z = e0.z + e1.z; P.w = e0.w + e1.w;
                Q.x = e0.x - e1.x; Q.y = e0.y - e1.y; Q.z = e0.z - e1.z; Q.w = e0.w - e1.w;
            }
            *(float4*)&plb[(ul * 2 + 0) * 128 + c4] = P;
            *(float4*)&plb[(ul * 2 + 1) * 128 + c4] = Q;
        }
        float* twb = TW + buf * 2048;
        #pragma unroll
        for (int r = 0; r < 2; r++) {
            int f = tid + 128 * r;
            int row = f >> 4, c4 = (f & 15) * 4;
            *(float4*)&twb[(row * 2 + 0) * 64 + c4] = *(const float4*)&Tmain[(u0 + row) * 64 + c4];
            if (hf)
                *(float4*)&twb[(row * 2 + 1) * 64 + c4] = *(const float4*)&Tsec[(u0 + row) * 64 + c4];
        }
    };

    if (half) {
        load(0, 0, true);
        __syncthreads();
        #pragma unroll 1
        for (int ks = 0; ks < 16; ks++) {
            int buf = ks & 1;
            if (ks + 1 < 16) load(ks + 1, buf ^ 1, true);
            float* plb = PL + buf * 4096;
            float* twb = TW + buf * 2048;
            #pragma unroll
            for (int kk = 0; kk < 16; kk++) {
                float av[8], bv[8], ca[8], cb[8];
                *(float4*)&av[0] = *(float4*)&plb[kk * 256 + ry];
                *(float4*)&av[4] = *(float4*)&plb[kk * 256 + ry + 4];
                *(float4*)&bv[0] = *(float4*)&plb[kk * 256 + 128 + ry];
                *(float4*)&bv[4] = *(float4*)&plb[kk * 256 + 128 + ry + 4];
                *(float4*)&ca[0] = *(float4*)&twb[kk * 128 + rx];
                *(float4*)&ca[4] = *(float4*)&twb[kk * 128 + rx + 4];
                *(float4*)&cb[0] = *(float4*)&twb[kk * 128 + 64 + rx];
                *(float4*)&cb[4] = *(float4*)&twb[kk * 128 + 64 + rx + 4];
                #pragma unroll
                for (int i = 0; i < 8; i++)
                    #pragma unroll
                    for (int j = 0; j < 8; j++)
                        acc[i][j] += av[i] * ca[j] + bv[i] * cb[j];
            }
            __syncthreads();
        }
    } else {
        load(0, 0, false);
        __syncthreads();
        #pragma unroll 1
        for (int ks = 0; ks < 16; ks++) {
            int buf = ks & 1;
            if (ks + 1 < 16) load(ks + 1, buf ^ 1, false);
            float* plb = PL + buf * 4096;
            float* twb = TW + buf * 2048;
            #pragma unroll
            for (int kk = 0; kk < 16; kk++) {
                float av[8], bv[8];
                *(float4*)&av[0] = *(float4*)&plb[kk * 256 + pl * 128 + ry];
                *(float4*)&av[4] = *(float4*)&plb[kk * 256 + pl * 128 + ry + 4];
                *(float4*)&bv[0] = *(float4*)&twb[kk * 128 + rx];
                *(float4*)&bv[4] = *(float4*)&twb[kk * 128 + rx + 4];
                #pragma unroll
                for (int i = 0; i < 8; i++)
                    #pragma unroll
                    for (int j = 0; j < 8; j++)
                        acc[i][j] += av[i] * bv[j];
            }
            __syncthreads();
        }
    }

    int nc[8];
    #pragma unroll
    for (int j = 0; j < 8; j++) nc[j] = ncol[rx + j];
    float* dst = outp + ((size_t)b * HE + he0 + ry) * M2;
    #pragma unroll
    for (int i = 0; i < 8; i++)
        #pragma unroll
        for (int j = 0; j < 8; j++)
            dst[(size_t)i * M2 + nc[j]] = acc[i][j];
}

// ---------------- stage2+3: qk GEMM + tanh + kv GEMM -----------------------
__global__ __launch_bounds__(256) void stage23_k() {
    extern __shared__ float sm[];
    float* Qs  = sm;            // [64][128]  32KB
    float* Ks  = sm + 8192;     // [64][128]  32KB
    float* qkr = sm;            // alias over Qs (after sync)
    float* qki = sm + 4096;

    const int h = blockIdx.x, b = blockIdx.y;
    const int tid = threadIdx.x;

    const float* Qg = d_Qf + ((size_t)b * HE + h * E_) * M2;
    const float* Kg = d_Kf + ((size_t)b * HE + h * E_) * M2;
    for (int i = tid; i < E_ * M2 / 4; i += 256) {
        ((float4*)Qs)[i] = ((const float4*)Qg)[i];
        ((float4*)Ks)[i] = ((const float4*)Kg)[i];
    }
    __syncthreads();

    // ---- stage 2 ----
    const int x0 = (tid & 15) * 4;
    {
        int y0 = (tid >> 4) * 4;
        float ar[4][4], ai[4][4];
        #pragma unroll
        for (int yy = 0; yy < 4; yy++)
            #pragma unroll
            for (int xx = 0; xx < 4; xx++) { ar[yy][xx] = 0.f; ai[yy][xx] = 0.f; }
        #pragma unroll 4
        for (int e = 0; e < 64; e++) {
            float4 q4r = *(float4*)&Qs[e * 128 + x0];
            float4 q4i = *(float4*)&Qs[e * 128 + 64 + x0];
            float4 k4r = *(float4*)&Ks[e * 128 + y0];
            float4 k4i = *(float4*)&Ks[e * 128 + 64 + y0];
            float qrv[4] = {q4r.x,q4r.y,q4r.z,q4r.w};
            float qiv[4] = {q4i.x,q4i.y,q4i.z,q4i.w};
            float krv[4] = {k4r.x,k4r.y,k4r.z,k4r.w};
            float kiv[4] = {k4i.x,k4i.y,k4i.z,k4i.w};
            #pragma unroll
            for (int yy = 0; yy < 4; yy++)
                #pragma unroll
                for (int xx = 0; xx < 4; xx++) {
                    ar[yy][xx] += qrv[xx]*krv[yy] - qiv[xx]*kiv[yy];
                    ai[yy][xx] += qrv[xx]*kiv[yy] + qiv[xx]*krv[yy];
                }
        }
        __syncthreads();   // all Qs reads done before aliased write
        #pragma unroll
        for (int yy = 0; yy < 4; yy++)
            #pragma unroll
            for (int xx = 0; xx < 4; xx++) {
                qkr[(y0 + yy) * 64 + x0 + xx] = tanhf(ar[yy][xx]);
                qki[(y0 + yy) * 64 + x0 + xx] = tanhf(ai[yy][xx]);
            }
    }
    __syncthreads();

    // ---- stage 3: kv[e,x], write to d_KV[(h*64+x)][c][b*64+e] -------------
    {
        int e0 = (tid >> 4) * 4;
        float cr[4][4], ci[4][4];
        #pragma unroll
        for (int ee = 0; ee < 4; ee++)
            #pragma unroll
            for (int xx = 0; xx < 4; xx++) { cr[ee][xx] = 0.f; ci[ee][xx] = 0.f; }
        #pragma unroll 4
        for (int y = 0; y < 64; y++) {
            float4 q4r = *(float4*)&qkr[y * 64 + x0];
            float4 q4i = *(float4*)&qki[y * 64 + x0];
            float qrv[4] = {q4r.x,q4r.y,q4r.z,q4r.w};
            float qiv[4] = {q4i.x,q4i.y,q4i.z,q4i.w};
            float krv[4], kiv[4];
            #pragma unroll
            for (int ee = 0; ee < 4; ee++) {
                krv[ee] = Ks[(e0 + ee) * 128 + y];
                kiv[ee] = Ks[(e0 + ee) * 128 + 64 + y];
            }
            #pragma unroll
            for (int ee = 0; ee < 4; ee++)
                #pragma unroll
                for (int xx = 0; xx < 4; xx++) {
                    cr[ee][xx] += qrv[xx]*krv[ee] - qiv[xx]*kiv[ee];
                    ci[ee][xx] += qrv[xx]*kiv[ee] + qiv[xx]*krv[ee];
                }
        }
        #pragma unroll
        for (int xx = 0; xx < 4; xx++) {
            size_t base = ((size_t)(h * 64 + x0 + xx) * 2) * 2048 + b * 64 + e0;
            *(float4*)&d_KV[base]        = make_float4(cr[0][xx], cr[1][xx], cr[2][xx], cr[3][xx]);
            *(float4*)&d_KV[base + 2048] = make_float4(ci[0][xx], ci[1][xx], ci[2][xx], ci[3][xx]);
        }
    }
}

// ---------------- stage4: per-(h,mode) pointwise complex GEMM --------------
// X2[b,o] = S * sum_e kv[b,e] * w[e,o]   (complex), w read once total.
__global__ __launch_bounds__(128) void xw_k() {
    extern __shared__ float sm[];
    float* kvS = sm;         // [e][c][b]  4096 floats
    float* wS  = sm + 4096;  // [e][c][o]  8192 floats
    const int x = blockIdx.x, h = blockIdx.y;
    const int tid = threadIdx.x;

    {
        const float4* kb = (const float4*)(d_KV + ((size_t)(h * 64 + x) * 2) * 2048);
        #pragma unroll
        for (int r = 0; r < 8; r++) {
            int idx4 = tid + 128 * r;              // 0..1023
            float4 v = kb[idx4];
            int e4 = idx4 & 15, bb = (idx4 >> 4) & 31, c = idx4 >> 9;
            #pragma unroll
            for (int j = 0; j < 4; j++)
                kvS[((e4 * 4 + j) * 2 + c) * 32 + bb] = (&v.x)[j];
        }
        const float4* wrb = (const float4*)(d_WTr + (size_t)(h * 64 + x) * 4096);
        const float4* wib = (const float4*)(d_WTi + (size_t)(h * 64 + x) * 4096);
        #pragma unroll
        for (int r = 0; r < 8; r++) {
            int idx4 = tid + 128 * r;              // 0..1023
            int e = idx4 >> 4, o4 = idx4 & 15;
            *(float4*)&wS[(e * 2 + 0) * 64 + o4 * 4] = wrb[idx4];
            *(float4*)&wS[(e * 2 + 1) * 64 + o4 * 4] = wib[idx4];
        }
    }
    __syncthreads();

    const int b0 = (tid >> 4) * 4;
    const int o0 = (tid & 15) * 4;
    float cr[4][4], ci[4][4];
    #pragma unroll
    for (int i = 0; i < 4; i++)
        #pragma unroll
        for (int j = 0; j < 4; j++) { cr[i][j] = 0.f; ci[i][j] = 0.f; }

    #pragma unroll 4
    for (int e = 0; e < 64; e++) {
        float4 kr4 = *(float4*)&kvS[(e * 2 + 0) * 32 + b0];
        float4 ki4 = *(float4*)&kvS[(e * 2 + 1) * 32 + b0];
        float4 wr4 = *(float4*)&wS[(e * 2 + 0) * 64 + o0];
        float4 wi4 = *(float4*)&wS[(e * 2 + 1) * 64 + o0];
        float kr[4] = {kr4.x,kr4.y,kr4.z,kr4.w};
        float ki[4] = {ki4.x,ki4.y,ki4.z,ki4.w};
        float wr[4] = {wr4.x,wr4.y,wr4.z,wr4.w};
        float wi[4] = {wi4.x,wi4.y,wi4.z,wi4.w};
        #pragma unroll
        for (int i = 0; i < 4; i++)
            #pragma unroll
            for (int j = 0; j < 4; j++) {
                cr[i][j] += kr[i]*wr[j] - ki[i]*wi[j];
                ci[i][j] += kr[i]*wi[j] + ki[i]*wr[j];
            }
    }
    __syncthreads();

    // stage results to smem (reuse wS), then coalesced global write
    const float S = 1.0f / 262144.0f;
    #pragma unroll
    for (int i = 0; i < 4; i++) {
        *(float4*)&wS[(0 * 32 + b0 + i) * 64 + o0] =
            make_float4(cr[i][0]*S, cr[i][1]*S, cr[i][2]*S, cr[i][3]*S);
        *(float4*)&wS[(1 * 32 + b0 + i) * 64 + o0] =
            make_float4(ci[i][0]*S, ci[i][1]*S, ci[i][2]*S, ci[i][3]*S);
    }
    __syncthreads();

    int slot = d_pos2slot_q[x];
    #pragma unroll
    for (int r = 0; r < 8; r++) {
        int idx4 = tid + 128 * r;                  // 0..1023
        int c = idx4 >> 9, bb = (idx4 >> 4) & 31, o4 = idx4 & 15;
        *(float4*)&d_X2T[(size_t)(2 * slot + c) * 16384 + (bb * 8 + h) * 64 + o4 * 4] =
            ((float4*)wS)[idx4];
    }
}

// ---------------- inverse: folded irfft ------------------------------------
__global__ __launch_bounds__(256) void inv_fold_k(float* __restrict__ outp) {
    extern __shared__ float sm[];
    float* Ys = sm;             // [64 rows][128 cols]
    float* Rr = sm + 8192;
    float* Ri = sm + 12288;
    float* Ir = sm + 16384;
    float* Ii = sm + 18432;
    const int u0 = blockIdx.x * 64;
    const int r0 = blockIdx.y * 64;
    const int tid = threadIdx.x;

    {
        for (int i = tid; i < 2048; i += 256) {
            int p = i >> 4, r4 = (i & 15) * 4;
            float4 v = *(const float4*)&d_X2T[(size_t)p * 16384 + r0 + r4];
            Ys[(r4 + 0) * 128 + p] = v.x;
            Ys[(r4 + 1) * 128 + p] = v.y;
            Ys[(r4 + 2) * 128 + p] = v.z;
            Ys[(r4 + 3) * 128 + p] = v.w;
        }
        for (int i = tid; i < 1024; i += 256) {
            int s = i >> 4, c4 = (i & 15) * 4;
            *(float4*)&Rr[s * 64 + c4] = *(const float4*)&d_TRr[s * 256 + u0 + c4];
            *(float4*)&Ri[s * 64 + c4] = *(const float4*)&d_TRi[s * 256 + u0 + c4];
        }
        for (int i = tid; i < 512; i += 256) {
            int s = i >> 4, c4 = (i & 15) * 4;
            *(float4*)&Ir[s * 64 + c4] = *(const float4*)&d_TIr[s * 256 + u0 + c4];
            *(float4*)&Ii[s * 64 + c4] = *(const float4*)&d_TIi[s * 256 + u0 + c4];
        }
    }
    __syncthreads();

    const int rr = (tid >> 4) * 4;
    const int uu = (tid & 15) * 4;
    float R0[4][4] = {}, R2[4][4] = {}, R1[4][4] = {}, I1[4][4] = {}, R3[4][4] = {}, I3[4][4] = {};

    const int n0 = d_bnd_q[0], n1 = d_bnd_q[1];

#define ACC_R(S, AR) { \
    float4 c4v = *(float4*)&Rr[(S) * 64 + uu]; \
    float4 d4v = *(float4*)&Ri[(S) * 64 + uu]; \
    float cv[4] = {c4v.x,c4v.y,c4v.z,c4v.w}; \
    float dv[4] = {d4v.x,d4v.y,d4v.z,d4v.w}; \
    _Pragma("unroll") \
    for (int r_ = 0; r_ < 4; r_++) { \
        float2 y = *(float2*)&Ys[(rr + r_) * 128 + 2 * (S)]; \
        _Pragma("unroll") \
        for (int u_ = 0; u_ < 4; u_++) AR[r_][u_] += y.x * cv[u_] + y.y * dv[u_]; \
    } }

#define ACC_RI(S, AR, AI) { \
    float4 c4v = *(float4*)&Rr[(S) * 64 + uu]; \
    float4 d4v = *(float4*)&Ri[(S) * 64 + uu]; \
    float4 e4v = *(float4*)&Ir[((S) - 32) * 64 + uu]; \
    float4 f4v = *(float4*)&Ii[((S) - 32) * 64 + uu]; \
    float cv[4] = {c4v.x,c4v.y,c4v.z,c4v.w}; \
    float dv[4] = {d4v.x,d4v.y,d4v.z,d4v.w}; \
    float ev[4] = {e4v.x,e4v.y,e4v.z,e4v.w}; \
    float fv[4] = {f4v.x,f4v.y,f4v.z,f4v.w}; \
    _Pragma("unroll") \
    for (int r_ = 0; r_ < 4; r_++) { \
        float2 y = *(float2*)&Ys[(rr + r_) * 128 + 2 * (S)]; \
        _Pragma("unroll") \
        for (int u_ = 0; u_ < 4; u_++) { \
            AR[r_][u_] += y.x * cv[u_] + y.y * dv[u_]; \
            AI[r_][u_] += y.x * ev[u_] + y.y * fv[u_]; \
        } \
    } }

    for (int s = 0; s < n0; s++)  ACC_R(s, R0);
    for (int s = n0; s < 32; s++) ACC_R(s, R2);
    for (int s = 32; s < n1; s++) ACC_RI(s, R1, I1);
    for (int s = n1; s < 64; s++) ACC_RI(s, R3, I3);

#undef ACC_R
#undef ACC_RI

    #pragma unroll
    for (int r_ = 0; r_ < 4; r_++) {
        float o0[4], o1[4], o2[4], o3[4];
        #pragma unroll
        for (int u_ = 0; u_ < 4; u_++) {
            float rp = R0[r_][u_] + R2[r_][u_];
            float rm = R0[r_][u_] - R2[r_][u_];
            o0[u_] = rp + R1[r_][u_] + R3[r_][u_];
            o1[u_] = rm - I1[r_][u_] + I3[r_][u_];
            o2[u_] = rp - R1[r_][u_] - R3[r_][u_];
            o3[u_] = rm + I1[r_][u_] - I3[r_][u_];
        }
        float* dst = outp + (size_t)(r0 + rr + r_) * L_ + u0 + uu;
        *(float4*)(dst + 0)   = make_float4(o0[0], o0[1], o0[2], o0[3]);
        *(float4*)(dst + 256) = make_float4(o1[0], o1[1], o1[2], o1[3]);
        *(float4*)(dst + 512) = make_float4(o2[0], o2[1], o2[2], o2[3]);
        *(float4*)(dst + 768) = make_float4(o3[0], o3[1], o3[2], o3[3]);
    }
}

// ---------------- launch ---------------------------------------------------
extern "C" void kernel_launch(void* const* d_in, const int* in_sizes, int n_in,
                              void* d_out, int out_size) {
    const float* q   = (const float*)d_in[0];
    const float* k   = (const float*)d_in[1];
    const float* wr  = (const float*)d_in[4];
    const float* wi  = (const float*)d_in[5];
    const int*   iq  = (const int*)d_in[6];
    const int*   ikv = (const int*)d_in[7];
    float* out = (float*)d_out;

    meta_k<<<2, 64>>>(iq, ikv);
    tables_k<<<256, 64>>>();
    wtrans_k<<<dim3(4, 64, 8), 256>>>(wr, wi);
    cudaFuncSetAttribute(dft_fold_k, cudaFuncAttributeMaxDynamicSharedMemorySize, 49152);
    dft_fold_k<<<dim3(8, B_, 2), 128, 49152>>>(q, k);
    cudaFuncSetAttribute(stage23_k, cudaFuncAttributeMaxDynamicSharedMemorySize, 65536);
    stage23_k<<<dim3(H_, B_), 256, 65536>>>();
    cudaFuncSetAttribute(xw_k, cudaFuncAttributeMaxDynamicSharedMemorySize, 49152);
    xw_k<<<dim3(64, 8), 128, 49152>>>();
    cudaFuncSetAttribute(inv_fold_k, cudaFuncAttributeMaxDynamicSharedMemorySize, 81920);
    inv_fold_k<<<dim3(4, 256), 256, 81920>>>(out);
}

// round 4
// speedup vs baseline: 1.6230x; 1.2656x over previous
#include <cuda_runtime.h>
#include <math.h>

#define B_    32
#define H_    8
#define E_    64
#define M_    64
#define L_    1024
#define DOUT_ 64
#define HE    512
#define M2    128

// ---------------- device scratch ----------------
__device__ float d_QfP[2][B_ * HE * M2];      // q spectrum partials (usplit)
__device__ float d_KfP[2][B_ * HE * M2];      // k spectrum partials
__device__ float d_KV[512 * 2 * 2048];        // kv: [(h*64+x)][c][b*64+e]
__device__ float d_WTr[8 * 64 * 64 * 64];     // wT [h][m][e][o]
__device__ float d_WTi[8 * 64 * 64 * 64];
__device__ float d_X2T[128 * 16384];          // X2 transposed: [2*slot+c][(b*8+h)*64+o]

// forward fold twiddles
__device__ float d_TEq[256 * 64], d_TAq[256 * 64], d_TBq[256 * 64];
__device__ float d_TEk[256 * 64], d_TAk[256 * 64], d_TBk[256 * 64];
// inverse tables
__device__ float d_TRr[64 * 256], d_TRi[64 * 256], d_TIr[32 * 256], d_TIi[32 * 256];
// meta
__device__ int d_slotm_q[64], d_slotm_k[64];
__device__ int d_evplane_q[32], d_evplane_k[32];
__device__ int d_ncolE_q[64], d_ncolO_q[64], d_ncolE_k[64], d_ncolO_k[64];
__device__ int d_pos2slot_q[64];
__device__ int d_bnd_q[2];

// ---------------- meta: parallel class-sort (order 0,2,1,3) ---------------
__global__ void meta_k(const int* __restrict__ iq, const int* __restrict__ ikv) {
    int z = blockIdx.x, j = threadIdx.x;
    __shared__ int mA[64], s2p[64], keys[64];
    const int* ix = z ? ikv : iq;
    mA[j] = ix[j];
    __syncthreads();
    int m = mA[j], c = m & 3;
    int oidx = (c == 0) ? 0 : ((c == 2) ? 1 : ((c == 1) ? 2 : 3));
    keys[j] = oidx * 64 + j;
    __syncthreads();
    int key = keys[j], slot = 0;
    for (int t = 0; t < 64; t++) slot += (keys[t] < key);
    (z ? d_slotm_k : d_slotm_q)[slot] = m;
    s2p[slot] = j;
    if (slot < 32) (z ? d_evplane_k : d_evplane_q)[slot] = (c == 2) ? 1 : 0;
    if (!z) d_pos2slot_q[j] = slot;
    __syncthreads();
    int* ncE = z ? d_ncolE_k : d_ncolE_q;
    int* ncO = z ? d_ncolO_k : d_ncolO_q;
    ncE[j] = (j < 32 ? 0 : 64) + s2p[j & 31];
    ncO[j] = (j < 32 ? 0 : 64) + s2p[32 + (j & 31)];
    if (!z && j == 0) {
        int c0 = 0, c1 = 0, c2 = 0;
        for (int t = 0; t < 64; t++) {
            int cc = mA[t] & 3;
            c0 += (cc == 0); c1 += (cc == 1); c2 += (cc == 2);
        }
        d_bnd_q[0] = c0;
        d_bnd_q[1] = c0 + c2 + c1;
    }
}

// ---------------- tables (fp64 accurate) ----------------------------------
__global__ void tables_k() {
    int t = blockIdx.x;
    int j = threadIdx.x;
    const double C = 6.283185307179586476925286766559 / (double)L_;
    for (int z = 0; z < 2; z++) {
        const int* slotm = z ? d_slotm_k : d_slotm_q;
        float* TE = z ? d_TEk : d_TEq;
        float* TA = z ? d_TAk : d_TAq;
        float* TB = z ? d_TBk : d_TBq;
        int m = slotm[j];
        double th = C * (double)((m * t) & (L_ - 1));
        double cs = cos(th), sn = sin(th);
        if (j < 32) {
            TE[t * 64 + j]      = (float)cs;
            TE[t * 64 + 32 + j] = (float)(-sn);
        } else {
            int s = j - 32;
            TA[t * 64 + s]      = (float)cs;
            TA[t * 64 + 32 + s] = (float)(-sn);
            double sg = ((m & 3) == 1) ? -1.0 : 1.0;
            TB[t * 64 + s]      = (float)(sg * sn);
            TB[t * 64 + 32 + s] = (float)(sg * cs);
        }
    }
    {
        int m = d_slotm_q[j];
        double th = C * (double)((m * t) & (L_ - 1));
        double g = ((m == 0) || (2 * m == L_)) ? (1.0 / L_) : (2.0 / L_);
        d_TRr[j * 256 + t] = (float)( g * cos(th));
        d_TRi[j * 256 + t] = (float)(-g * sin(th));
        if (j >= 32) {
            d_TIr[(j - 32) * 256 + t] = (float)(g * sin(th));
            d_TIi[(j - 32) * 256 + t] = (float)(g * cos(th));
        }
    }
}

// ---------------- w transpose: (H,E,DOUT,M) -> (H,M,E,DOUT) ----------------
__global__ __launch_bounds__(256) void wtrans_k(const float* __restrict__ wr_g,
                                                const float* __restrict__ wi_g) {
    __shared__ float tile[32][33];
    const int ot = (blockIdx.x & 1) * 32;
    const int mt = (blockIdx.x >> 1) * 32;
    const int e  = blockIdx.y;
    const int h  = blockIdx.z;
    const int r  = threadIdx.x >> 3;
    const int c4 = (threadIdx.x & 7) * 4;

    for (int z = 0; z < 2; z++) {
        const float* src = z ? wi_g : wr_g;
        float* dst = z ? d_WTi : d_WTr;
        float4 v = *(const float4*)&src[((size_t)(h * 64 + e) * 64 + ot + r) * 64 + mt + c4];
        tile[r][c4 + 0] = v.x; tile[r][c4 + 1] = v.y;
        tile[r][c4 + 2] = v.z; tile[r][c4 + 3] = v.w;
        __syncthreads();
        float4 o;
        o.x = tile[c4 + 0][r]; o.y = tile[c4 + 1][r];
        o.z = tile[c4 + 2][r]; o.w = tile[c4 + 3][r];
        *(float4*)&dst[((size_t)(h * 64 + mt + r) * 64 + e) * 64 + ot + c4] = o;
        __syncthreads();
    }
}

// ---------------- forward: folded partial DFT, occupancy-tuned -------------
// blockIdx.x bits: b0=half (0 even cols, 1 odd), b1=usplit, >>2 heTile (0..7)
// Block: 128 threads, tile 64he x 64cols, 128 u-rows (8 ks of 16).
__global__ __launch_bounds__(128) void dft_fold_k(const float* __restrict__ qg,
                                                  const float* __restrict__ kg) {
    extern __shared__ float sm[];
    float* PL = sm;          // [2 buf][16 u][2 pl][64 he]  = 2*2048 floats
    float* TW = sm + 4096;   // [2 buf][16 u][128 cols]      = 2*2048 floats
    const int half   = blockIdx.x & 1;
    const int us     = (blockIdx.x >> 1) & 1;
    const int heTile = blockIdx.x >> 2;
    const int b      = blockIdx.y;
    const int zin    = blockIdx.z;
    const float* __restrict__ x = zin ? kg : qg;
    float* outp = zin ? d_KfP[us] : d_QfP[us];
    const float* __restrict__ Tmain = half ? (zin ? d_TAk : d_TAq) : (zin ? d_TEk : d_TEq);
    const float* __restrict__ Tsec  = zin ? d_TBk : d_TBq;
    const int* __restrict__ ncol = half ? (zin ? d_ncolO_k : d_ncolO_q)
                                        : (zin ? d_ncolE_k : d_ncolE_q);
    const int he0 = heTile * 64;
    const int tid = threadIdx.x;
    const int cx  = (tid & 15) * 4;   // col group (4 cols)
    const int ryy = (tid >> 4) * 8;   // row group (8 rows)
    const int plA = half ? 0 : (zin ? d_evplane_k : d_evplane_q)[cx & 31];
    const int ubase = us * 128;
    const float* xb = x + (size_t)b * (L_ * HE) + he0;

    float acc[8][4];
    #pragma unroll
    for (int i = 0; i < 8; i++)
        #pragma unroll
        for (int j = 0; j < 4; j++) acc[i][j] = 0.f;

    auto load = [&](int ks, int buf) {
        int u0 = ubase + ks * 16;
        float* plb = PL + buf * 2048;
        #pragma unroll
        for (int r = 0; r < 2; r++) {
            int idx = tid + 128 * r;     // 0..255
            int ul  = idx >> 4;          // 16 u-rows
            int c4  = (idx & 15) * 4;    // 64 he
            const float* p = xb + (size_t)(u0 + ul) * HE + c4;
            float4 x0 = *(const float4*)p;
            float4 x1 = *(const float4*)(p + 256 * HE);
            float4 x2 = *(const float4*)(p + 512 * HE);
            float4 x3 = *(const float4*)(p + 768 * HE);
            float4 P, Q;
            if (half) {
                P.x = x0.x - x2.x; P.y = x0.y - x2.y; P.z = x0.z - x2.z; P.w = x0.w - x2.w;
                Q.x = x1.x - x3.x; Q.y = x1.y - x3.y; Q.z = x1.z - x3.z; Q.w = x1.w - x3.w;
            } else {
                float4 e0, e1;
                e0.x = x0.x + x2.x; e0.y = x0.y + x2.y; e0.z = x0.z + x2.z; e0.w = x0.w + x2.w;
                e1.x = x1.x + x3.x; e1.y = x1.y + x3.y; e1.z = x1.z + x3.z; e1.w = x1.w + x3.w;
                P.x = e0.x + e1.x; P.y = e0.y + e1.y; P.z = e0.z + e1.z; P.w = e0.w + e1.w;
                Q.x = e0.x - e1.x; Q.y = e0.y - e1.y; Q.z = e0.z - e1.z; Q.w = e0.w - e1.w;
            }
            *(float4*)&plb[(ul * 2 + 0) * 64 + c4] = P;
            *(float4*)&plb[(ul * 2 + 1) * 64 + c4] = Q;
        }
        float* twb = TW + buf * 2048;
        #pragma unroll
        for (int r = 0; r < 2; r++) {
            int f = tid + 128 * r;       // 0..255
            int row = f >> 4, c4 = (f & 15) * 4;
            *(float4*)&twb[row * 128 + c4] = *(const float4*)&Tmain[(u0 + row) * 64 + c4];
        }
        if (half) {
            #pragma unroll
            for (int r = 0; r < 2; r++) {
                int f = tid + 128 * r;
                int row = f >> 4, c4 = (f & 15) * 4;
                *(float4*)&twb[row * 128 + 64 + c4] = *(const float4*)&Tsec[(u0 + row) * 64 + c4];
            }
        }
    };

    load(0, 0);
    __syncthreads();
    #pragma unroll 1
    for (int ks = 0; ks < 8; ks++) {
        int buf = ks & 1;
        if (ks + 1 < 8) load(ks + 1, buf ^ 1);
        float* plb = PL + buf * 2048;
        float* twb = TW + buf * 2048;
        if (half) {
            #pragma unroll
            for (int kk = 0; kk < 16; kk++) {
                float av[8], aw[8], bv[4], cw[4];
                *(float4*)&av[0] = *(float4*)&plb[(kk * 2 + 0) * 64 + ryy];
                *(float4*)&av[4] = *(float4*)&plb[(kk * 2 + 0) * 64 + ryy + 4];
                *(float4*)&aw[0] = *(float4*)&plb[(kk * 2 + 1) * 64 + ryy];
                *(float4*)&aw[4] = *(float4*)&plb[(kk * 2 + 1) * 64 + ryy + 4];
                *(float4*)&bv[0] = *(float4*)&twb[kk * 128 + cx];
                *(float4*)&cw[0] = *(float4*)&twb[kk * 128 + 64 + cx];
                #pragma unroll
                for (int i = 0; i < 8; i++)
                    #pragma unroll
                    for (int j = 0; j < 4; j++)
                        acc[i][j] += av[i] * bv[j] + aw[i] * cw[j];
            }
        } else {
            #pragma unroll
            for (int kk = 0; kk < 16; kk++) {
                float av[8], bv[4];
                *(float4*)&av[0] = *(float4*)&plb[(kk * 2 + plA) * 64 + ryy];
                *(float4*)&av[4] = *(float4*)&plb[(kk * 2 + plA) * 64 + ryy + 4];
                *(float4*)&bv[0] = *(float4*)&twb[kk * 128 + cx];
                #pragma unroll
                for (int i = 0; i < 8; i++)
                    #pragma unroll
                    for (int j = 0; j < 4; j++)
                        acc[i][j] += av[i] * bv[j];
            }
        }
        __syncthreads();
    }

    int nc[4];
    #pragma unroll
    for (int j = 0; j < 4; j++) nc[j] = ncol[cx + j];
    float* dst = outp + ((size_t)b * HE + he0 + ryy) * M2;
    #pragma unroll
    for (int i = 0; i < 8; i++)
        #pragma unroll
        for (int j = 0; j < 4; j++)
            dst[(size_t)i * M2 + nc[j]] = acc[i][j];
}

// ---------------- stage2+3: qk GEMM + tanh + kv GEMM -----------------------
__global__ __launch_bounds__(256) void stage23_k() {
    extern __shared__ float sm[];
    float* Qs  = sm;            // [64][128]
    float* Ks  = sm + 8192;
    float* qkr = sm;            // alias over Qs (after sync)
    float* qki = sm + 4096;

    const int h = blockIdx.x, b = blockIdx.y;
    const int tid = threadIdx.x;

    const size_t off4 = (((size_t)b * HE + h * E_) * M2) / 4;
    const float4* Q0 = ((const float4*)d_QfP[0]) + off4;
    const float4* Q1 = ((const float4*)d_QfP[1]) + off4;
    const float4* K0 = ((const float4*)d_KfP[0]) + off4;
    const float4* K1 = ((const float4*)d_KfP[1]) + off4;
    for (int i = tid; i < E_ * M2 / 4; i += 256) {
        float4 a = Q0[i], bb = Q1[i];
        ((float4*)Qs)[i] = make_float4(a.x + bb.x, a.y + bb.y, a.z + bb.z, a.w + bb.w);
        float4 c = K0[i], d = K1[i];
        ((float4*)Ks)[i] = make_float4(c.x + d.x, c.y + d.y, c.z + d.z, c.w + d.w);
    }
    __syncthreads();

    const int x0 = (tid & 15) * 4;
    {
        int y0 = (tid >> 4) * 4;
        float ar[4][4], ai[4][4];
        #pragma unroll
        for (int yy = 0; yy < 4; yy++)
            #pragma unroll
            for (int xx = 0; xx < 4; xx++) { ar[yy][xx] = 0.f; ai[yy][xx] = 0.f; }
        #pragma unroll 4
        for (int e = 0; e < 64; e++) {
            float4 q4r = *(float4*)&Qs[e * 128 + x0];
            float4 q4i = *(float4*)&Qs[e * 128 + 64 + x0];
            float4 k4r = *(float4*)&Ks[e * 128 + y0];
            float4 k4i = *(float4*)&Ks[e * 128 + 64 + y0];
            float qrv[4] = {q4r.x,q4r.y,q4r.z,q4r.w};
            float qiv[4] = {q4i.x,q4i.y,q4i.z,q4i.w};
            float krv[4] = {k4r.x,k4r.y,k4r.z,k4r.w};
            float kiv[4] = {k4i.x,k4i.y,k4i.z,k4i.w};
            #pragma unroll
            for (int yy = 0; yy < 4; yy++)
                #pragma unroll
                for (int xx = 0; xx < 4; xx++) {
                    ar[yy][xx] += qrv[xx]*krv[yy] - qiv[xx]*kiv[yy];
                    ai[yy][xx] += qrv[xx]*kiv[yy] + qiv[xx]*krv[yy];
                }
        }
        __syncthreads();
        #pragma unroll
        for (int yy = 0; yy < 4; yy++)
            #pragma unroll
            for (int xx = 0; xx < 4; xx++) {
                qkr[(y0 + yy) * 64 + x0 + xx] = tanhf(ar[yy][xx]);
                qki[(y0 + yy) * 64 + x0 + xx] = tanhf(ai[yy][xx]);
            }
    }
    __syncthreads();

    {
        int e0 = (tid >> 4) * 4;
        float cr[4][4], ci[4][4];
        #pragma unroll
        for (int ee = 0; ee < 4; ee++)
            #pragma unroll
            for (int xx = 0; xx < 4; xx++) { cr[ee][xx] = 0.f; ci[ee][xx] = 0.f; }
        #pragma unroll 4
        for (int y = 0; y < 64; y++) {
            float4 q4r = *(float4*)&qkr[y * 64 + x0];
            float4 q4i = *(float4*)&qki[y * 64 + x0];
            float qrv[4] = {q4r.x,q4r.y,q4r.z,q4r.w};
            float qiv[4] = {q4i.x,q4i.y,q4i.z,q4i.w};
            float krv[4], kiv[4];
            #pragma unroll
            for (int ee = 0; ee < 4; ee++) {
                krv[ee] = Ks[(e0 + ee) * 128 + y];
                kiv[ee] = Ks[(e0 + ee) * 128 + 64 + y];
            }
            #pragma unroll
            for (int ee = 0; ee < 4; ee++)
                #pragma unroll
                for (int xx = 0; xx < 4; xx++) {
                    cr[ee][xx] += qrv[xx]*krv[ee] - qiv[xx]*kiv[ee];
                    ci[ee][xx] += qrv[xx]*kiv[ee] + qiv[xx]*krv[ee];
                }
        }
        #pragma unroll
        for (int xx = 0; xx < 4; xx++) {
            size_t base = ((size_t)(h * 64 + x0 + xx) * 2) * 2048 + b * 64 + e0;
            *(float4*)&d_KV[base]        = make_float4(cr[0][xx], cr[1][xx], cr[2][xx], cr[3][xx]);
            *(float4*)&d_KV[base + 2048] = make_float4(ci[0][xx], ci[1][xx], ci[2][xx], ci[3][xx]);
        }
    }
}

// ---------------- stage4: per-(h,mode) pointwise complex GEMM --------------
__global__ __launch_bounds__(128) void xw_k() {
    extern __shared__ float sm[];
    float* kvS = sm;         // [e][c][b]
    float* wS  = sm + 4096;  // [e][c][o]
    const int x = blockIdx.x, h = blockIdx.y;
    const int tid = threadIdx.x;

    {
        const float4* kb = (const float4*)(d_KV + ((size_t)(h * 64 + x) * 2) * 2048);
        #pragma unroll
        for (int r = 0; r < 8; r++) {
            int idx4 = tid + 128 * r;
            float4 v = kb[idx4];
            int e4 = idx4 & 15, bb = (idx4 >> 4) & 31, c = idx4 >> 9;
            #pragma unroll
            for (int j = 0; j < 4; j++)
                kvS[((e4 * 4 + j) * 2 + c) * 32 + bb] = (&v.x)[j];
        }
        const float4* wrb = (const float4*)(d_WTr + (size_t)(h * 64 + x) * 4096);
        const float4* wib = (const float4*)(d_WTi + (size_t)(h * 64 + x) * 4096);
        #pragma unroll
        for (int r = 0; r < 8; r++) {
            int idx4 = tid + 128 * r;
            int e = idx4 >> 4, o4 = idx4 & 15;
            *(float4*)&wS[(e * 2 + 0) * 64 + o4 * 4] = wrb[idx4];
            *(float4*)&wS[(e * 2 + 1) * 64 + o4 * 4] = wib[idx4];
        }
    }
    __syncthreads();

    const int b0 = (tid >> 4) * 4;
    const int o0 = (tid & 15) * 4;
    float cr[4][4], ci[4][4];
    #pragma unroll
    for (int i = 0; i < 4; i++)
        #pragma unroll
        for (int j = 0; j < 4; j++) { cr[i][j] = 0.f; ci[i][j] = 0.f; }

    #pragma unroll 4
    for (int e = 0; e < 64; e++) {
        float4 kr4 = *(float4*)&kvS[(e * 2 + 0) * 32 + b0];
        float4 ki4 = *(float4*)&kvS[(e * 2 + 1) * 32 + b0];
        float4 wr4 = *(float4*)&wS[(e * 2 + 0) * 64 + o0];
        float4 wi4 = *(float4*)&wS[(e * 2 + 1) * 64 + o0];
        float kr[4] = {kr4.x,kr4.y,kr4.z,kr4.w};
        float ki[4] = {ki4.x,ki4.y,ki4.z,ki4.w};
        float wr[4] = {wr4.x,wr4.y,wr4.z,wr4.w};
        float wi[4] = {wi4.x,wi4.y,wi4.z,wi4.w};
        #pragma unroll
        for (int i = 0; i < 4; i++)
            #pragma unroll
            for (int j = 0; j < 4; j++) {
                cr[i][j] += kr[i]*wr[j] - ki[i]*wi[j];
                ci[i][j] += kr[i]*wi[j] + ki[i]*wr[j];
            }
    }
    __syncthreads();

    const float S = 1.0f / 262144.0f;
    #pragma unroll
    for (int i = 0; i < 4; i++) {
        *(float4*)&wS[(0 * 32 + b0 + i) * 64 + o0] =
            make_float4(cr[i][0]*S, cr[i][1]*S, cr[i][2]*S, cr[i][3]*S);
        *(float4*)&wS[(1 * 32 + b0 + i) * 64 + o0] =
            make_float4(ci[i][0]*S, ci[i][1]*S, ci[i][2]*S, ci[i][3]*S);
    }
    __syncthreads();

    int slot = d_pos2slot_q[x];
    #pragma unroll
    for (int r = 0; r < 8; r++) {
        int idx4 = tid + 128 * r;
        int c = idx4 >> 9, bb = (idx4 >> 4) & 31, o4 = idx4 & 15;
        *(float4*)&d_X2T[(size_t)(2 * slot + c) * 16384 + (bb * 8 + h) * 64 + o4 * 4] =
            ((float4*)wS)[idx4];
    }
}

// ---------------- inverse: folded irfft ------------------------------------
__global__ __launch_bounds__(256) void inv_fold_k(float* __restrict__ outp) {
    extern __shared__ float sm[];
    float* Ys = sm;
    float* Rr = sm + 8192;
    float* Ri = sm + 12288;
    float* Ir = sm + 16384;
    float* Ii = sm + 18432;
    const int u0 = blockIdx.x * 64;
    const int r0 = blockIdx.y * 64;
    const int tid = threadIdx.x;

    {
        for (int i = tid; i < 2048; i += 256) {
            int p = i >> 4, r4 = (i & 15) * 4;
            float4 v = *(const float4*)&d_X2T[(size_t)p * 16384 + r0 + r4];
            Ys[(r4 + 0) * 128 + p] = v.x;
            Ys[(r4 + 1) * 128 + p] = v.y;
            Ys[(r4 + 2) * 128 + p] = v.z;
            Ys[(r4 + 3) * 128 + p] = v.w;
        }
        for (int i = tid; i < 1024; i += 256) {
            int s = i >> 4, c4 = (i & 15) * 4;
            *(float4*)&Rr[s * 64 + c4] = *(const float4*)&d_TRr[s * 256 + u0 + c4];
            *(float4*)&Ri[s * 64 + c4] = *(const float4*)&d_TRi[s * 256 + u0 + c4];
        }
        for (int i = tid; i < 512; i += 256) {
            int s = i >> 4, c4 = (i & 15) * 4;
            *(float4*)&Ir[s * 64 + c4] = *(const float4*)&d_TIr[s * 256 + u0 + c4];
            *(float4*)&Ii[s * 64 + c4] = *(const float4*)&d_TIi[s * 256 + u0 + c4];
        }
    }
    __syncthreads();

    const int rr = (tid >> 4) * 4;
    const int uu = (tid & 15) * 4;
    float R0[4][4] = {}, R2[4][4] = {}, R1[4][4] = {}, I1[4][4] = {}, R3[4][4] = {}, I3[4][4] = {};

    const int n0 = d_bnd_q[0], n1 = d_bnd_q[1];

#define ACC_R(S, AR) { \
    float4 c4v = *(float4*)&Rr[(S) * 64 + uu]; \
    float4 d4v = *(float4*)&Ri[(S) * 64 + uu]; \
    float cv[4] = {c4v.x,c4v.y,c4v.z,c4v.w}; \
    float dv[4] = {d4v.x,d4v.y,d4v.z,d4v.w}; \
    _Pragma("unroll") \
    for (int r_ = 0; r_ < 4; r_++) { \
        float2 y = *(float2*)&Ys[(rr + r_) * 128 + 2 * (S)]; \
        _Pragma("unroll") \
        for (int u_ = 0; u_ < 4; u_++) AR[r_][u_] += y.x * cv[u_] + y.y * dv[u_]; \
    } }

#define ACC_RI(S, AR, AI) { \
    float4 c4v = *(float4*)&Rr[(S) * 64 + uu]; \
    float4 d4v = *(float4*)&Ri[(S) * 64 + uu]; \
    float4 e4v = *(float4*)&Ir[((S) - 32) * 64 + uu]; \
    float4 f4v = *(float4*)&Ii[((S) - 32) * 64 + uu]; \
    float cv[4] = {c4v.x,c4v.y,c4v.z,c4v.w}; \
    float dv[4] = {d4v.x,d4v.y,d4v.z,d4v.w}; \
    float ev[4] = {e4v.x,e4v.y,e4v.z,e4v.w}; \
    float fv[4] = {f4v.x,f4v.y,f4v.z,f4v.w}; \
    _Pragma("unroll") \
    for (int r_ = 0; r_ < 4; r_++) { \
        float2 y = *(float2*)&Ys[(rr + r_) * 128 + 2 * (S)]; \
        _Pragma("unroll") \
        for (int u_ = 0; u_ < 4; u_++) { \
            AR[r_][u_] += y.x * cv[u_] + y.y * dv[u_]; \
            AI[r_][u_] += y.x * ev[u_] + y.y * fv[u_]; \
        } \
    } }

    for (int s = 0; s < n0; s++)  ACC_R(s, R0);
    for (int s = n0; s < 32; s++) ACC_R(s, R2);
    for (int s = 32; s < n1; s++) ACC_RI(s, R1, I1);
    for (int s = n1; s < 64; s++) ACC_RI(s, R3, I3);

#undef ACC_R
#undef ACC_RI

    #pragma unroll
    for (int r_ = 0; r_ < 4; r_++) {
        float o0[4], o1[4], o2[4], o3[4];
        #pragma unroll
        for (int u_ = 0; u_ < 4; u_++) {
            float rp = R0[r_][u_] + R2[r_][u_];
            float rm = R0[r_][u_] - R2[r_][u_];
            o0[u_] = rp + R1[r_][u_] + R3[r_][u_];
            o1[u_] = rm - I1[r_][u_] + I3[r_][u_];
            o2[u_] = rp - R1[r_][u_] - R3[r_][u_];
            o3[u_] = rm + I1[r_][u_] - I3[r_][u_];
        }
        float* dst = outp + (size_t)(r0 + rr + r_) * L_ + u0 + uu;
        *(float4*)(dst + 0)   = make_float4(o0[0], o0[1], o0[2], o0[3]);
        *(float4*)(dst + 256) = make_float4(o1[0], o1[1], o1[2], o1[3]);
        *(float4*)(dst + 512) = make_float4(o2[0], o2[1], o2[2], o2[3]);
        *(float4*)(dst + 768) = make_float4(o3[0], o3[1], o3[2], o3[3]);
    }
}

// ---------------- launch ---------------------------------------------------
extern "C" void kernel_launch(void* const* d_in, const int* in_sizes, int n_in,
                              void* d_out, int out_size) {
    const float* q   = (const float*)d_in[0];
    const float* k   = (const float*)d_in[1];
    const float* wr  = (const float*)d_in[4];
    const float* wi  = (const float*)d_in[5];
    const int*   iq  = (const int*)d_in[6];
    const int*   ikv = (const int*)d_in[7];
    float* out = (float*)d_out;

    meta_k<<<2, 64>>>(iq, ikv);
    tables_k<<<256, 64>>>();
    wtrans_k<<<dim3(4, 64, 8), 256>>>(wr, wi);
    cudaFuncSetAttribute(dft_fold_k, cudaFuncAttributeMaxDynamicSharedMemorySize, 32768);
    dft_fold_k<<<dim3(32, B_, 2), 128, 32768>>>(q, k);
    cudaFuncSetAttribute(stage23_k, cudaFuncAttributeMaxDynamicSharedMemorySize, 65536);
    stage23_k<<<dim3(H_, B_), 256, 65536>>>();
    cudaFuncSetAttribute(xw_k, cudaFuncAttributeMaxDynamicSharedMemorySize, 49152);
    xw_k<<<dim3(64, 8), 128, 49152>>>();
    cudaFuncSetAttribute(inv_fold_k, cudaFuncAttributeMaxDynamicSharedMemorySize, 81920);
    inv_fold_k<<<dim3(4, 256), 256, 81920>>>(out);
}